// round 1
// baseline (speedup 1.0000x reference)
#include <cuda_runtime.h>
#include <math.h>

#define BATCH 8
#define SEQ 1024
#define DMODEL 768
#define NHEAD 16
#define HDIM 48
#define MROWS (BATCH*SEQ)

// Scratch (allocation-free rule: device globals)
__device__ float g_Q[MROWS*DMODEL];   // [B,H,S,PD]
__device__ float g_K[MROWS*DMODEL];   // [B,H,S,PD]
__device__ float g_V[MROWS*DMODEL];   // [B,H,S,PD]
__device__ float g_A[MROWS*DMODEL];   // [B,S,D] attention output (pre O-proj)

// ---------------- GEMM core: 64x64 tile, BK=16, 256 threads, 4x4 micro-tile ----
#define GBM 64
#define GBN 64
#define GBK 16

__device__ __forceinline__ void gemm_core(const float* __restrict__ X,
                                          const float* __restrict__ W,
                                          int mTile, int nTile,
                                          float acc[4][4],
                                          float As[GBK][GBM+1],
                                          float Bs[GBK][GBN+1])
{
    const int tid = threadIdx.x;
    const int tx = tid & 15, ty = tid >> 4;
    for (int k0 = 0; k0 < DMODEL; k0 += GBK) {
        // A tile: 64 rows x 16 k.  thread: row = tid/4, k-quad = (tid%4)*4 (float4)
        {
            int am = tid >> 2, ak = (tid & 3) << 2;
            float4 a = *reinterpret_cast<const float4*>(
                X + (size_t)(mTile + am) * DMODEL + k0 + ak);
            As[ak+0][am] = a.x; As[ak+1][am] = a.y;
            As[ak+2][am] = a.z; As[ak+3][am] = a.w;
        }
        // B tile: 16 k-rows x 64 n.  thread: r = tid/16, c = (tid%16)*4 (float4)
        {
            int br = tid >> 4, bc = (tid & 15) << 2;
            float4 b = *reinterpret_cast<const float4*>(
                W + (size_t)(k0 + br) * DMODEL + nTile + bc);
            Bs[br][bc+0] = b.x; Bs[br][bc+1] = b.y;
            Bs[br][bc+2] = b.z; Bs[br][bc+3] = b.w;
        }
        __syncthreads();
        #pragma unroll
        for (int kk = 0; kk < GBK; kk++) {
            float ar[4], br4[4];
            #pragma unroll
            for (int i = 0; i < 4; i++) ar[i] = As[kk][ty*4 + i];
            #pragma unroll
            for (int j = 0; j < 4; j++) br4[j] = Bs[kk][tx*4 + j];
            #pragma unroll
            for (int i = 0; i < 4; i++)
                #pragma unroll
                for (int j = 0; j < 4; j++)
                    acc[i][j] = fmaf(ar[i], br4[j], acc[i][j]);
        }
        __syncthreads();
    }
}

// ---------------- QKV projection: out remapped to [B,H,S,PD] -------------------
__global__ __launch_bounds__(256)
void qkv_kernel(const float* __restrict__ X,
                const float* __restrict__ Wq, const float* __restrict__ bq,
                const float* __restrict__ Wk, const float* __restrict__ bk,
                const float* __restrict__ Wv, const float* __restrict__ bv)
{
    __shared__ float As[GBK][GBM+1];
    __shared__ float Bs[GBK][GBN+1];

    const float* W; const float* bias; float* out;
    if (blockIdx.z == 0)      { W = Wq; bias = bq; out = g_Q; }
    else if (blockIdx.z == 1) { W = Wk; bias = bk; out = g_K; }
    else                      { W = Wv; bias = bv; out = g_V; }

    const int mTile = blockIdx.y * GBM;
    const int nTile = blockIdx.x * GBN;

    float acc[4][4] = {};
    gemm_core(X, W, mTile, nTile, acc, As, Bs);

    const int tx = threadIdx.x & 15, ty = threadIdx.x >> 4;
    #pragma unroll
    for (int i = 0; i < 4; i++) {
        int m = mTile + ty*4 + i;
        int b = m / SEQ, s = m % SEQ;
        #pragma unroll
        for (int j = 0; j < 4; j++) {
            int n = nTile + tx*4 + j;
            int h = n / HDIM, pd = n % HDIM;
            out[(((size_t)b*NHEAD + h)*SEQ + s)*HDIM + pd] = acc[i][j] + bias[n];
        }
    }
}

// ---------------- Flash attention: 64 q-rows x 32 k-cols tiles ------------------
#define AM 64
#define AN 32

__global__ __launch_bounds__(256)
void attn_kernel()
{
    __shared__ float sQ[AM][HDIM+1];
    __shared__ float sK[AN][HDIM+1];
    __shared__ float sV[AN][HDIM+1];
    __shared__ float sS[AM][AN+1];

    const int bh = blockIdx.y;            // 0..127 = b*NHEAD + h
    const int q0 = blockIdx.x * AM;
    const float* Qp = g_Q + (size_t)bh * SEQ * HDIM;
    const float* Kp = g_K + (size_t)bh * SEQ * HDIM;
    const float* Vp = g_V + (size_t)bh * SEQ * HDIM;

    const int tid = threadIdx.x;

    // Load Q tile (64 x 48)
    for (int i = tid; i < AM*HDIM; i += 256)
        sQ[i/HDIM][i%HDIM] = Qp[(size_t)(q0 + i/HDIM)*HDIM + (i%HDIM)];

    const int r  = tid >> 2;              // q-row 0..63
    const int qd = tid & 3;               // quad lane: owns 8 score cols, 12 O cols

    float m_i = -1e30f, l_i = 0.f;
    float acc[12];
    #pragma unroll
    for (int j = 0; j < 12; j++) acc[j] = 0.f;

    const float scale = rsqrtf((float)HDIM);

    for (int kt = 0; kt < SEQ/AN; kt++) {
        __syncthreads();                  // prior-iter sS/sK/sV reads done (also fences sQ load)
        for (int i = tid; i < AN*HDIM; i += 256) {
            int rr = i / HDIM, dd = i % HDIM;
            sK[rr][dd] = Kp[(size_t)(kt*AN + rr)*HDIM + dd];
            sV[rr][dd] = Vp[(size_t)(kt*AN + rr)*HDIM + dd];
        }
        __syncthreads();

        // Scores: this thread computes 8 of the 64x32 tile (row r, cols qd*8..)
        float sv[8];
        float mloc = -1e30f;
        #pragma unroll
        for (int jj = 0; jj < 8; jj++) {
            int c = qd*8 + jj;
            float s = 0.f;
            #pragma unroll
            for (int d = 0; d < HDIM; d++)
                s = fmaf(sQ[r][d], sK[c][d], s);
            s *= scale;
            sv[jj] = s;
            mloc = fmaxf(mloc, s);
        }
        // quad-reduce row max (lanes of a quad are consecutive)
        mloc = fmaxf(mloc, __shfl_xor_sync(0xffffffffu, mloc, 1));
        mloc = fmaxf(mloc, __shfl_xor_sync(0xffffffffu, mloc, 2));
        float m_new = fmaxf(m_i, mloc);
        float corr  = __expf(m_i - m_new);

        float lloc = 0.f;
        #pragma unroll
        for (int jj = 0; jj < 8; jj++) {
            float p = __expf(sv[jj] - m_new);
            sS[r][qd*8 + jj] = p;
            lloc += p;
        }
        lloc += __shfl_xor_sync(0xffffffffu, lloc, 1);
        lloc += __shfl_xor_sync(0xffffffffu, lloc, 2);
        l_i = l_i * corr + lloc;
        m_i = m_new;

        __syncthreads();                  // sS visible to all

        // O += P @ V   (this thread: row r, cols qd*12 .. qd*12+11)
        #pragma unroll
        for (int j = 0; j < 12; j++) acc[j] *= corr;
        #pragma unroll
        for (int n = 0; n < AN; n++) {
            float p = sS[r][n];
            #pragma unroll
            for (int j = 0; j < 12; j++)
                acc[j] = fmaf(p, sV[n][qd*12 + j], acc[j]);
        }
    }

    // Normalize and write to [B,S,D] for the O projection
    const int b = bh / NHEAD, h = bh % NHEAD;
    const float inv = 1.f / l_i;
    const size_t base = ((size_t)b*SEQ + q0 + r)*DMODEL + h*HDIM + qd*12;
    #pragma unroll
    for (int j = 0; j < 12; j++)
        g_A[base + j] = acc[j] * inv;
}

// ---------------- Output projection ---------------------------------------------
__global__ __launch_bounds__(256)
void oproj_kernel(float* __restrict__ out,
                  const float* __restrict__ Wo, const float* __restrict__ bo)
{
    __shared__ float As[GBK][GBM+1];
    __shared__ float Bs[GBK][GBN+1];

    const int mTile = blockIdx.y * GBM;
    const int nTile = blockIdx.x * GBN;

    float acc[4][4] = {};
    gemm_core(g_A, Wo, mTile, nTile, acc, As, Bs);

    const int tx = threadIdx.x & 15, ty = threadIdx.x >> 4;
    #pragma unroll
    for (int i = 0; i < 4; i++) {
        int m = mTile + ty*4 + i;
        #pragma unroll
        for (int j = 0; j < 4; j++) {
            int n = nTile + tx*4 + j;
            out[(size_t)m*DMODEL + n] = acc[i][j] + bo[n];
        }
    }
}

// ---------------- Launch ---------------------------------------------------------
extern "C" void kernel_launch(void* const* d_in, const int* in_sizes, int n_in,
                              void* d_out, int out_size)
{
    const float* X  = (const float*)d_in[0];
    const float* Wq = (const float*)d_in[1];
    const float* bq = (const float*)d_in[2];
    const float* Wk = (const float*)d_in[3];
    const float* bk = (const float*)d_in[4];
    const float* Wv = (const float*)d_in[5];
    const float* bv = (const float*)d_in[6];
    const float* Wo = (const float*)d_in[7];
    const float* bo = (const float*)d_in[8];
    float* out = (float*)d_out;

    dim3 gQKV(DMODEL/GBN, MROWS/GBM, 3);          // 12 x 128 x 3
    qkv_kernel<<<gQKV, 256>>>(X, Wq, bq, Wk, bk, Wv, bv);

    dim3 gAttn(SEQ/AM, BATCH*NHEAD);              // 16 x 128
    attn_kernel<<<gAttn, 256>>>();

    dim3 gO(DMODEL/GBN, MROWS/GBM);               // 12 x 128
    oproj_kernel<<<gO, 256>>>(out, Wo, bo);
}